// round 1
// baseline (speedup 1.0000x reference)
#include <cuda_runtime.h>
#include <cuda_bf16.h>

// Problem constants (fixed by the dataset)
#define C_SAMPLES 500000
#define H_DIM 6
#define F_DIM 6
#define K_BINS 4
#define HIST_SIZE 16777216   // 4^12 floats
#define HIST_F4   (HIST_SIZE / 4)

__global__ void zero_hist_kernel(float4* __restrict__ out) {
    int i = blockIdx.x * blockDim.x + threadIdx.x;
    if (i < HIST_F4) out[i] = make_float4(0.f, 0.f, 0.f, 0.f);
}

__device__ __forceinline__ int bin_of(float v, float b) {
    int i = __float2int_rz(v + b);   // trunc toward zero, matches astype(int32)
    i = max(i, 0);
    return min(i, K_BINS - 1);
}

__global__ void hist_kernel(const float4* __restrict__ in,   // (C, 6, 4) -> 6 float4 per row
                            const float4* __restrict__ outp, // (C, 6, 4)
                            const float4* __restrict__ bi,
                            const float4* __restrict__ bo,
                            float* __restrict__ hist,
                            float invC) {
    int c = blockIdx.x * blockDim.x + threadIdx.x;
    if (c >= C_SAMPLES) return;

    unsigned lin0 = 0, lin1 = 0, lin2 = 0, lin3 = 0;

    const float4* pv = in  + c * H_DIM;
    const float4* pb = bi  + c * H_DIM;
#pragma unroll
    for (int h = 0; h < H_DIM; ++h) {
        float4 v = pv[h];
        float4 b = pb[h];
        lin0 = (lin0 << 2) | (unsigned)bin_of(v.x, b.x);
        lin1 = (lin1 << 2) | (unsigned)bin_of(v.y, b.y);
        lin2 = (lin2 << 2) | (unsigned)bin_of(v.z, b.z);
        lin3 = (lin3 << 2) | (unsigned)bin_of(v.w, b.w);
    }

    pv = outp + c * F_DIM;
    pb = bo   + c * F_DIM;
#pragma unroll
    for (int f = 0; f < F_DIM; ++f) {
        float4 v = pv[f];
        float4 b = pb[f];
        lin0 = (lin0 << 2) | (unsigned)bin_of(v.x, b.x);
        lin1 = (lin1 << 2) | (unsigned)bin_of(v.y, b.y);
        lin2 = (lin2 << 2) | (unsigned)bin_of(v.z, b.z);
        lin3 = (lin3 << 2) | (unsigned)bin_of(v.w, b.w);
    }

    atomicAdd(hist + lin0, invC);
    atomicAdd(hist + lin1, invC);
    atomicAdd(hist + lin2, invC);
    atomicAdd(hist + lin3, invC);
}

extern "C" void kernel_launch(void* const* d_in, const int* in_sizes, int n_in,
                              void* d_out, int out_size) {
    const float4* in   = (const float4*)d_in[0];
    const float4* outp = (const float4*)d_in[1];
    const float4* bi   = (const float4*)d_in[2];
    const float4* bo   = (const float4*)d_in[3];
    float* hist = (float*)d_out;

    (void)in_sizes; (void)n_in; (void)out_size;

    // Phase 1: zero the 16.7M-bin histogram (default-stream ordering serializes
    // this before the scatter kernel).
    zero_hist_kernel<<<HIST_F4 / 256, 256>>>((float4*)hist);

    // Phase 2: streaming read of all four tensors, bit-pack the 12 base-4
    // digits, scatter-add 1/C per point.
    const float invC = 1.0f / (float)C_SAMPLES;
    int blocks = (C_SAMPLES + 255) / 256;
    hist_kernel<<<blocks, 256>>>(in, outp, bi, bo, hist, invC);
}